// round 1
// baseline (speedup 1.0000x reference)
#include <cuda_runtime.h>

// Problem constants
#define Bz    8
#define Nn    1024
#define DIMm  512
#define Hh    8
#define DHd   64
#define INNERi 512
#define NPp   1025     // 2*MAX_POS + 1
#define BHb   64       // Bz*Hh
#define MXm   8192     // Bz*Nn

// ---------------- device scratch (allocation-free rule: static globals) ----
__device__ float g_q  [(size_t)BHb * Nn * DHd];      // [b][h][n][d]   16.8 MB
__device__ float g_k  [(size_t)BHb * Nn * DHd];
__device__ float g_v  [(size_t)BHb * Nn * DHd];
__device__ float g_P  [(size_t)BHb * Nn * NPp];      // q . pos_table  268.7 MB
__device__ float g_S  [(size_t)BHb * Nn * Nn];       // scores/attn    268.4 MB
__device__ float g_ctx[(size_t)MXm * INNERi];        // [b][n][h][d]   16.8 MB

// ===========================================================================
// Kernel 1: fused QKV projection.
//   C[8192,1536] = x[8192,512] @ [Wq | Wkv]   then scatter into head layout.
// 64x64 tile, BK=16, 256 threads, 4x4 micro-tile.
// ===========================================================================
__global__ void qkv_kernel(const float* __restrict__ x,
                           const float* __restrict__ Wq,
                           const float* __restrict__ Wkv) {
    __shared__ __align__(16) float As[16][68];
    __shared__ __align__(16) float Bs[16][64];

    const int n0 = blockIdx.x * 64;   // 0..1535
    const int m0 = blockIdx.y * 64;   // 0..8191
    const int t  = threadIdx.x;
    const int tx = t & 15, ty = t >> 4;

    const float* Wsrc; int ldw, cbase;
    float* dst; int jbase;
    if (n0 < 512)       { Wsrc = Wq;  ldw = 512;  cbase = n0;       dst = g_q; jbase = 0;    }
    else if (n0 < 1024) { Wsrc = Wkv; ldw = 1024; cbase = n0 - 512; dst = g_k; jbase = 512;  }
    else                { Wsrc = Wkv; ldw = 1024; cbase = n0 - 512; dst = g_v; jbase = 1024; }

    float acc[4][4] = {};

    for (int k0 = 0; k0 < 512; k0 += 16) {
        #pragma unroll
        for (int i = 0; i < 4; i++) {
            int l = t + i * 256;
            int mm = l >> 4, kk = l & 15;
            As[kk][mm] = x[(m0 + mm) * 512 + k0 + kk];
        }
        #pragma unroll
        for (int i = 0; i < 4; i++) {
            int l = t + i * 256;
            int kk = l >> 6, nn = l & 63;
            Bs[kk][nn] = Wsrc[(k0 + kk) * ldw + cbase + nn];
        }
        __syncthreads();
        #pragma unroll
        for (int kk = 0; kk < 16; kk++) {
            float4 a4 = *(const float4*)&As[kk][ty * 4];
            float4 b4 = *(const float4*)&Bs[kk][tx * 4];
            float a[4] = {a4.x, a4.y, a4.z, a4.w};
            float b[4] = {b4.x, b4.y, b4.z, b4.w};
            #pragma unroll
            for (int ii = 0; ii < 4; ii++)
                #pragma unroll
                for (int jj = 0; jj < 4; jj++)
                    acc[ii][jj] += a[ii] * b[jj];
        }
        __syncthreads();
    }

    #pragma unroll
    for (int ii = 0; ii < 4; ii++) {
        int m  = m0 + ty * 4 + ii;
        int bb = m >> 10, nrow = m & 1023;
        #pragma unroll
        for (int jj = 0; jj < 4; jj++) {
            int j = n0 + tx * 4 + jj - jbase;    // 0..511 within region
            int h = j >> 6, d = j & 63;
            dst[(((size_t)(bb * 8 + h) * Nn + nrow) * DHd) + d] = acc[ii][jj];
        }
    }
}

// ===========================================================================
// Kernel 2: P[m,p] = q[m,:] . pos_table[p,:]   (m = bh*N + n, K = 64)
// ===========================================================================
__global__ void pos_gemm_kernel(const float* __restrict__ T) {
    __shared__ __align__(16) float Qs[64][68];
    __shared__ __align__(16) float Ts[64][68];

    const int p0 = blockIdx.x * 64;   // 0..1088 (17 tiles, last partial)
    const int m0 = blockIdx.y * 64;   // 0..65535
    const int t  = threadIdx.x;
    const int tx = t & 15, ty = t >> 4;

    #pragma unroll
    for (int i = 0; i < 16; i++) {
        int l = t + i * 256;
        int kk = l & 63, mm = l >> 6;
        Qs[kk][mm] = g_q[(size_t)(m0 + mm) * DHd + kk];
    }
    #pragma unroll
    for (int i = 0; i < 16; i++) {
        int l = t + i * 256;
        int kk = l & 63, nn = l >> 6;
        int p = p0 + nn;
        Ts[kk][nn] = (p < NPp) ? T[p * DHd + kk] : 0.0f;
    }
    __syncthreads();

    float acc[4][4] = {};
    #pragma unroll
    for (int kk = 0; kk < 64; kk++) {
        float4 a4 = *(const float4*)&Qs[kk][ty * 4];
        float4 b4 = *(const float4*)&Ts[kk][tx * 4];
        float a[4] = {a4.x, a4.y, a4.z, a4.w};
        float b[4] = {b4.x, b4.y, b4.z, b4.w};
        #pragma unroll
        for (int ii = 0; ii < 4; ii++)
            #pragma unroll
            for (int jj = 0; jj < 4; jj++)
                acc[ii][jj] += a[ii] * b[jj];
    }

    #pragma unroll
    for (int ii = 0; ii < 4; ii++) {
        int m = m0 + ty * 4 + ii;
        #pragma unroll
        for (int jj = 0; jj < 4; jj++) {
            int p = p0 + tx * 4 + jj;
            if (p < NPp) g_P[(size_t)m * NPp + p] = acc[ii][jj];
        }
    }
}

// ===========================================================================
// Kernel 3: S[bh,i,j] = scale * ( q_i . k_j  +  P[bh,i, clip(i-j)+512] )
// One 64x64 tile per block, K = 64 (single stage).
// ===========================================================================
__global__ void score_kernel(float scale) {
    __shared__ __align__(16) float Qs[64][68];
    __shared__ __align__(16) float Ks[64][68];

    const int j0 = blockIdx.x * 64;
    const int i0 = blockIdx.y * 64;
    const int bh = blockIdx.z;
    const int t  = threadIdx.x;
    const int tx = t & 15, ty = t >> 4;

    const float* qb = g_q + (size_t)bh * Nn * DHd;
    const float* kb = g_k + (size_t)bh * Nn * DHd;

    #pragma unroll
    for (int i = 0; i < 16; i++) {
        int l = t + i * 256;
        int kk = l & 63, mm = l >> 6;
        Qs[kk][mm] = qb[(i0 + mm) * DHd + kk];
    }
    #pragma unroll
    for (int i = 0; i < 16; i++) {
        int l = t + i * 256;
        int kk = l & 63, nn = l >> 6;
        Ks[kk][nn] = kb[(j0 + nn) * DHd + kk];
    }
    __syncthreads();

    float acc[4][4] = {};
    #pragma unroll
    for (int kk = 0; kk < 64; kk++) {
        float4 a4 = *(const float4*)&Qs[kk][ty * 4];
        float4 b4 = *(const float4*)&Ks[kk][tx * 4];
        float a[4] = {a4.x, a4.y, a4.z, a4.w};
        float b[4] = {b4.x, b4.y, b4.z, b4.w};
        #pragma unroll
        for (int ii = 0; ii < 4; ii++)
            #pragma unroll
            for (int jj = 0; jj < 4; jj++)
                acc[ii][jj] += a[ii] * b[jj];
    }

    const float* Pb = g_P + (size_t)bh * Nn * NPp;
    float* Sb = g_S + (size_t)bh * Nn * Nn;
    #pragma unroll
    for (int ii = 0; ii < 4; ii++) {
        int i = i0 + ty * 4 + ii;
        #pragma unroll
        for (int jj = 0; jj < 4; jj++) {
            int j = j0 + tx * 4 + jj;
            int delta = i - j;
            delta = max(-512, min(512, delta));
            float pv = Pb[(size_t)i * NPp + (delta + 512)];
            Sb[(size_t)i * Nn + j] = scale * (acc[ii][jj] + pv);
        }
    }
}

// ===========================================================================
// Kernel 4: row softmax over N=1024, in place on g_S. One block per row.
// ===========================================================================
__global__ void softmax_kernel() {
    __shared__ float redm[8];
    __shared__ float reds[8];
    const size_t row = blockIdx.x;
    float* S = g_S + row * (size_t)Nn;
    const int t = threadIdx.x;       // 256 threads * 4 floats
    const int lane = t & 31, warp = t >> 5;

    float4 v = *(float4*)(S + t * 4);
    float m = fmaxf(fmaxf(v.x, v.y), fmaxf(v.z, v.w));
    #pragma unroll
    for (int o = 16; o; o >>= 1) m = fmaxf(m, __shfl_xor_sync(0xffffffffu, m, o));
    if (lane == 0) redm[warp] = m;
    __syncthreads();
    float rowmax = redm[0];
    #pragma unroll
    for (int i = 1; i < 8; i++) rowmax = fmaxf(rowmax, redm[i]);

    float4 e;
    e.x = __expf(v.x - rowmax);
    e.y = __expf(v.y - rowmax);
    e.z = __expf(v.z - rowmax);
    e.w = __expf(v.w - rowmax);
    float s = e.x + e.y + e.z + e.w;
    #pragma unroll
    for (int o = 16; o; o >>= 1) s += __shfl_xor_sync(0xffffffffu, s, o);
    if (lane == 0) reds[warp] = s;
    __syncthreads();
    float tot = 0.0f;
    #pragma unroll
    for (int i = 0; i < 8; i++) tot += reds[i];
    float inv = 1.0f / tot;

    e.x *= inv; e.y *= inv; e.z *= inv; e.w *= inv;
    *(float4*)(S + t * 4) = e;
}

// ===========================================================================
// Kernel 5: ctx[b,n,h,d] = sum_j attn[bh,n,j] * v[bh,j,d]   (M=1024,N=64,K=1024)
// ===========================================================================
__global__ void av_kernel() {
    __shared__ __align__(16) float As[16][68];
    __shared__ __align__(16) float Vs[16][64];

    const int i0 = blockIdx.x * 64;
    const int bh = blockIdx.y;
    const int t  = threadIdx.x;
    const int tx = t & 15, ty = t >> 4;

    const float* Sb = g_S + (size_t)bh * Nn * Nn;
    const float* vb = g_v + (size_t)bh * Nn * DHd;

    float acc[4][4] = {};
    for (int k0 = 0; k0 < Nn; k0 += 16) {
        #pragma unroll
        for (int i = 0; i < 4; i++) {
            int l = t + i * 256;
            int mm = l >> 4, kk = l & 15;
            As[kk][mm] = Sb[(size_t)(i0 + mm) * Nn + k0 + kk];
        }
        #pragma unroll
        for (int i = 0; i < 4; i++) {
            int l = t + i * 256;
            int kk = l >> 6, nn = l & 63;
            Vs[kk][nn] = vb[(k0 + kk) * DHd + nn];
        }
        __syncthreads();
        #pragma unroll
        for (int kk = 0; kk < 16; kk++) {
            float4 a4 = *(const float4*)&As[kk][ty * 4];
            float4 b4 = *(const float4*)&Vs[kk][tx * 4];
            float a[4] = {a4.x, a4.y, a4.z, a4.w};
            float b[4] = {b4.x, b4.y, b4.z, b4.w};
            #pragma unroll
            for (int ii = 0; ii < 4; ii++)
                #pragma unroll
                for (int jj = 0; jj < 4; jj++)
                    acc[ii][jj] += a[ii] * b[jj];
        }
        __syncthreads();
    }

    const int b = bh >> 3, h = bh & 7;
    #pragma unroll
    for (int ii = 0; ii < 4; ii++) {
        int i = i0 + ty * 4 + ii;
        #pragma unroll
        for (int jj = 0; jj < 4; jj++) {
            int d = tx * 4 + jj;
            g_ctx[(((size_t)(b * Nn + i) * Hh + h) * DHd) + d] = acc[ii][jj];
        }
    }
}

// ===========================================================================
// Kernel 6: out[8192,512] = ctx[8192,512] @ Wo[512,512] + bo
// ===========================================================================
__global__ void out_gemm_kernel(const float* __restrict__ Wo,
                                const float* __restrict__ bo,
                                float* __restrict__ out) {
    __shared__ __align__(16) float As[16][68];
    __shared__ __align__(16) float Bs[16][64];

    const int n0 = blockIdx.x * 64;
    const int m0 = blockIdx.y * 64;
    const int t  = threadIdx.x;
    const int tx = t & 15, ty = t >> 4;

    float acc[4][4] = {};
    for (int k0 = 0; k0 < 512; k0 += 16) {
        #pragma unroll
        for (int i = 0; i < 4; i++) {
            int l = t + i * 256;
            int mm = l >> 4, kk = l & 15;
            As[kk][mm] = g_ctx[(size_t)(m0 + mm) * INNERi + k0 + kk];
        }
        #pragma unroll
        for (int i = 0; i < 4; i++) {
            int l = t + i * 256;
            int kk = l >> 6, nn = l & 63;
            Bs[kk][nn] = Wo[(k0 + kk) * DIMm + n0 + nn];
        }
        __syncthreads();
        #pragma unroll
        for (int kk = 0; kk < 16; kk++) {
            float4 a4 = *(const float4*)&As[kk][ty * 4];
            float4 b4 = *(const float4*)&Bs[kk][tx * 4];
            float a[4] = {a4.x, a4.y, a4.z, a4.w};
            float b[4] = {b4.x, b4.y, b4.z, b4.w};
            #pragma unroll
            for (int ii = 0; ii < 4; ii++)
                #pragma unroll
                for (int jj = 0; jj < 4; jj++)
                    acc[ii][jj] += a[ii] * b[jj];
        }
        __syncthreads();
    }

    #pragma unroll
    for (int ii = 0; ii < 4; ii++) {
        int m = m0 + ty * 4 + ii;
        #pragma unroll
        for (int jj = 0; jj < 4; jj++) {
            int n = n0 + tx * 4 + jj;
            out[(size_t)m * DIMm + n] = acc[ii][jj] + bo[n];
        }
    }
}

// ===========================================================================
extern "C" void kernel_launch(void* const* d_in, const int* in_sizes, int n_in,
                              void* d_out, int out_size) {
    const float* x   = (const float*)d_in[0];
    const float* Wq  = (const float*)d_in[1];
    const float* Wkv = (const float*)d_in[2];
    const float* Wo  = (const float*)d_in[3];
    const float* bo  = (const float*)d_in[4];
    const float* pos = (const float*)d_in[5];
    float* out = (float*)d_out;

    qkv_kernel     <<<dim3(24, 128), 256>>>(x, Wq, Wkv);
    pos_gemm_kernel<<<dim3(17, 1024), 256>>>(pos);
    score_kernel   <<<dim3(16, 16, 64), 256>>>(0.125f);   // 64^-0.5
    softmax_kernel <<<65536, 256>>>();
    av_kernel      <<<dim3(16, 64), 256>>>();
    out_gemm_kernel<<<dim3(8, 128), 256>>>(Wo, bo, out);
}